// round 10
// baseline (speedup 1.0000x reference)
#include <cuda_runtime.h>

#define BB 16
#define TT 96
#define TP1 97
#define HW 16384
#define NSTEP 6
#define MTHR 0.9f
#define NBLK 512
#define PXB 512             // pixels owned per block (both phases)
#define BPB 32              // blocks per batch

// ---- scratch (device globals; no allocation APIs) ----
__device__ float         g_D[(size_t)BB * HW * TT];  // d[b][p][t], t contiguous (~100MB)
__device__ double        g_part[BB * TT * BPB];      // [b][t][j]: per-block delta partials
__device__ unsigned char g_topcov[BB * HW];
__device__ float         g_topval[BB * HW];
__device__ int           g_bcnt[8];                  // barrier arrival counters (self-resetting)
__device__ int           g_bgen[8];                  // barrier generations (monotonic)

// ---------------------------------------------------------------------------
// Grid-wide sense-reversing barrier; gen is monotonic (graph-replay safe).
// All NBLK blocks co-resident: 4 blocks/SM * 148 SMs = 592 >= 512.
__device__ __forceinline__ void grid_barrier(int slot) {
    __syncthreads();
    __threadfence();
    if (threadIdx.x == 0) {
        int g   = atomicAdd(&g_bgen[slot], 0);
        int old = atomicAdd(&g_bcnt[slot], 1);
        if (old == NBLK - 1) {
            g_bcnt[slot] = 0;
            __threadfence();
            atomicExch(&g_bgen[slot], g + 1);
        } else {
            while (atomicAdd(&g_bgen[slot], 0) == g) __nanosleep(64);
        }
    }
    __syncthreads();
    __threadfence();
}

// ---------------------------------------------------------------------------
struct SmemPre { float xs[64]; float eb[64]; float dsm[64][TP1]; };
struct SmemStep { int list[PXB]; float partial[2][TT]; unsigned wm[8]; int scid; };
union SmemU { SmemPre pre; SmemStep st; };

__global__ void __launch_bounds__(256, 4)
k_all(const float* __restrict__ x,
      const float* __restrict__ temps,
      const float* __restrict__ msks,
      const float* __restrict__ bg,
      float* __restrict__ out) {
    __shared__ SmemU sm;
    __shared__ float  accd[TT];          // phase-A delta0 accumulator
    __shared__ double dpart[TT];         // this block's running delta partial
    __shared__ double sdelta[TP1];       // per-step summed delta (all candidates)
    __shared__ unsigned char used[TP1];

    const int tid = threadIdx.x;
    const int blk = blockIdx.x;
    const int b   = blk >> 5;            // 32 blocks per batch
    const int jj  = blk & 31;            // block index within batch
    const int p0g = jj * PXB;            // block's 512-pixel slice

    if (tid < TP1) used[tid] = 0;
    if (tid < TT)  accd[tid] = 0.f;

    // ============ Phase A: precompute D + delta0 on own 8 tiles =============
    for (int ti = 0; ti < 8; ti++) {
        const int p0 = p0g + ti * 64;

        if (tid < 64) {
            float xv = x[b * HW + p0 + tid];
            float bv = bg[p0 + tid];
            sm.pre.xs[tid] = xv;
            float e = xv - bv;
            sm.pre.eb[tid] = e * e;
            g_topcov[b * HW + p0 + tid] = 0;
        }
        __syncthreads();

        const int ts  = tid >> 4;        // 16 templates per iteration
        const int ps4 = tid & 15;        // float4 pixel group
        #pragma unroll
        for (int t16 = 0; t16 < TT; t16 += 16) {
            int t = t16 + ts;
            const size_t rb = (size_t)(b * TT + t) * HW + p0;
            float4 tv = __ldg((const float4*)(temps + rb) + ps4);
            float4 mv = __ldg((const float4*)(msks  + rb) + ps4);
            int p = 4 * ps4;
            float d0 = 0.f, d1 = 0.f, d2 = 0.f, d3 = 0.f;
            if (mv.x > MTHR) { float a = sm.pre.xs[p]     - tv.x * mv.x; d0 = a * a - sm.pre.eb[p];     }
            if (mv.y > MTHR) { float a = sm.pre.xs[p + 1] - tv.y * mv.y; d1 = a * a - sm.pre.eb[p + 1]; }
            if (mv.z > MTHR) { float a = sm.pre.xs[p + 2] - tv.z * mv.z; d2 = a * a - sm.pre.eb[p + 2]; }
            if (mv.w > MTHR) { float a = sm.pre.xs[p + 3] - tv.w * mv.w; d3 = a * a - sm.pre.eb[p + 3]; }
            sm.pre.dsm[p][t]     = d0;
            sm.pre.dsm[p + 1][t] = d1;
            sm.pre.dsm[p + 2][t] = d2;
            sm.pre.dsm[p + 3][t] = d3;
        }
        __syncthreads();

        const size_t obase = ((size_t)b * HW + p0) * TT;
        for (int i = tid; i < 64 * TT / 4; i += 256) {
            int r = i / 24, c = (i % 24) * 4;
            float4 v = make_float4(sm.pre.dsm[r][c], sm.pre.dsm[r][c + 1],
                                   sm.pre.dsm[r][c + 2], sm.pre.dsm[r][c + 3]);
            *(float4*)&g_D[obase + (size_t)i * 4] = v;
        }

        if (tid < TT) {
            float s = 0.f;
            #pragma unroll
            for (int p = 0; p < 64; p++) s += sm.pre.dsm[p][tid];
            accd[tid] += s;
        }
        __syncthreads();   // protect smem reuse next tile
    }
    if (tid < TT) {
        dpart[tid] = (double)accd[tid];
        g_part[(b * TT + tid) * BPB + jj] = dpart[tid];   // publish partial
    }

    grid_barrier(0);

    // ============ Phase B: 6 greedy steps on own 512 pixels ================
    for (int s = 0; s < NSTEP; s++) {
        // --- sum the 32 per-block partials for every candidate ---
        if (tid < TT) {
            const double* pp = &g_part[(b * TT + tid) * BPB];
            double s0 = 0.0, s1 = 0.0, s2 = 0.0, s3 = 0.0;
            #pragma unroll
            for (int j = 0; j < BPB; j += 4) {
                s0 += __ldcg(pp + j);
                s1 += __ldcg(pp + j + 1);
                s2 += __ldcg(pp + j + 2);
                s3 += __ldcg(pp + j + 3);
            }
            sdelta[tid + 1] = (s0 + s1) + (s2 + s3);
        }
        if (tid == 0) sdelta[0] = 0.0;   // empty template: delta always 0
        __syncthreads();

        // --- argmin over 97 candidates (redundant per block, identical) ---
        if (tid < 32) {
            double bestv = 1e300;
            int    besti = TP1;
            for (int t = tid; t < TP1; t += 32) {
                double v = used[t] ? 1e30 : sdelta[t];
                if (v < bestv) { bestv = v; besti = t; }   // earliest on tie
            }
            for (int off = 16; off; off >>= 1) {
                double ov = __shfl_down_sync(0xffffffffu, bestv, off);
                int    oi = __shfl_down_sync(0xffffffffu, besti, off);
                if (ov < bestv || (ov == bestv && oi < besti)) { bestv = ov; besti = oi; }
            }
            if (tid == 0) {
                sm.st.scid = besti;
                if (besti != 0) used[besti] = 1;
            }
        }
        __syncthreads();
        const int cid = sm.st.scid;

        // --- paint own pixels + deterministic compaction of new ones ---
        int base = 0;
        if (cid != 0) {
            const size_t mrow = (size_t)(b * TT + cid - 1) * HW;
            #pragma unroll
            for (int k = 0; k < PXB / 256; k++) {
                int lp = k * 256 + tid;
                int p  = p0g + lp;
                int q  = b * HW + p;
                bool nw = false;
                float mv = msks[mrow + p];
                if (mv > MTHR && !g_topcov[q]) {
                    g_topval[q] = temps[mrow + p] * mv;  // goes UNDER existing
                    g_topcov[q] = 1;
                    nw = true;
                }
                unsigned m = __ballot_sync(0xffffffffu, nw);
                if ((tid & 31) == 0) sm.st.wm[tid >> 5] = m;
                __syncthreads();
                int off = base, tot = 0;
                #pragma unroll
                for (int w = 0; w < 8; w++) {
                    int c = __popc(sm.st.wm[w]);
                    if (w < (tid >> 5)) off += c;
                    tot += c;
                }
                if (nw) sm.st.list[off + __popc(m & ((1u << (tid & 31)) - 1))] = lp;
                base += tot;
                __syncthreads();
            }
        }
        const int n = base;

        if (s == NSTEP - 1) {
            // --- final composition for own pixels ---
            #pragma unroll
            for (int k = 0; k < PXB / 256; k++) {
                int p = p0g + k * 256 + tid;
                int q = b * HW + p;
                out[q] = g_topcov[q] ? g_topval[q] : bg[p];
            }
        } else {
            // --- gather-subtract D rows of own new pixels (block-private) ---
            if (n > 0) {
                const int grp = tid >> 7;    // 0/1: even/odd list entries
                const int lt  = tid & 127;
                float a0 = 0.f, a1 = 0.f, a2 = 0.f, a3 = 0.f;
                if (lt < TT) {
                    const float* Db = g_D + ((size_t)b * HW + p0g) * TT + lt;
                    int j = grp;
                    for (; j + 6 < n; j += 8) {
                        a0 += Db[(size_t)sm.st.list[j    ] * TT];
                        a1 += Db[(size_t)sm.st.list[j + 2] * TT];
                        a2 += Db[(size_t)sm.st.list[j + 4] * TT];
                        a3 += Db[(size_t)sm.st.list[j + 6] * TT];
                    }
                    for (; j < n; j += 2) a0 += Db[(size_t)sm.st.list[j] * TT];
                    sm.st.partial[grp][lt] = (a0 + a1) + (a2 + a3);
                }
                __syncthreads();
                if (tid < TT) {
                    float tot2 = sm.st.partial[0][tid] + sm.st.partial[1][tid];
                    dpart[tid] -= (double)tot2;
                    g_part[(b * TT + tid) * BPB + jj] = dpart[tid];
                }
            }
            grid_barrier(1 + s);
        }
    }
}

// ---------------------------------------------------------------------------
extern "C" void kernel_launch(void* const* d_in, const int* in_sizes, int n_in,
                              void* d_out, int out_size) {
    const float* x      = (const float*)d_in[0];   // (16,1,128,128)
    const float* temps  = (const float*)d_in[1];   // (16,96,1,128,128)
    const float* msks   = (const float*)d_in[2];   // (16,96,1,128,128)
    const float* bg     = (const float*)d_in[3];   // (1,128,128)
    float* out = (float*)d_out;                    // (16,1,128,128)

    k_all<<<NBLK, 256>>>(x, temps, msks, bg, out);
}

// round 11
// speedup vs baseline: 1.2024x; 1.2024x over previous
#include <cuda_runtime.h>

#define BB 16
#define TT 96
#define TP1 97
#define HW 16384
#define NSTEP 6
#define MTHR 0.9f
#define NBLK 576            // <= 4 blocks/SM * 148 SMs = 592 (co-resident)
#define BPB 36              // blocks per batch
#define NTIL 256            // 64-pixel tiles per batch
#define LMAX 512            // max pixels per phase-B slice (456 actual)

// ---- scratch (device globals; no allocation APIs) ----
__device__ float         g_D[(size_t)BB * HW * TT];  // d[b][p][t], t contiguous (~100MB)
__device__ double        g_delta[BB * TP1];          // idx0 = empty template, always 0
__device__ unsigned char g_topcov[BB * HW];
__device__ float         g_topval[BB * HW];
__device__ int           g_bcnt[8];                  // barrier arrival counters (self-resetting)
__device__ int           g_bgen[8];                  // barrier generations (monotonic)

// ---------------------------------------------------------------------------
// Grid-wide sense-reversing barrier; gen is monotonic (graph-replay safe).
__device__ __forceinline__ void grid_barrier(int slot) {
    __syncthreads();
    __threadfence();
    if (threadIdx.x == 0) {
        int g   = atomicAdd(&g_bgen[slot], 0);
        int old = atomicAdd(&g_bcnt[slot], 1);
        if (old == NBLK - 1) {
            g_bcnt[slot] = 0;
            __threadfence();
            atomicExch(&g_bgen[slot], g + 1);
        } else {
            while (atomicAdd(&g_bgen[slot], 0) == g) __nanosleep(64);
        }
    }
    __syncthreads();
    __threadfence();
}

// ---------------------------------------------------------------------------
struct SmemPre { float xs[64]; float eb[64]; float dsm[64][TP1]; };
struct SmemStep { int list[LMAX]; float partial[2][TT]; unsigned wm[8]; int scid; };
union SmemU { SmemPre pre; SmemStep st; };

__global__ void __launch_bounds__(256, 4)
k_all(const float* __restrict__ x,
      const float* __restrict__ temps,
      const float* __restrict__ msks,
      const float* __restrict__ bg,
      float* __restrict__ out) {
    __shared__ SmemU sm;
    __shared__ float accd[TT];           // phase-A delta0 accumulator
    __shared__ unsigned char used[TP1];

    const int tid = threadIdx.x;
    const int blk = blockIdx.x;
    const int b   = blk / BPB;           // batch
    const int jj  = blk % BPB;           // block index within batch

    if (tid < TP1) used[tid] = 0;
    if (tid < TT)  accd[tid] = 0.f;

    // --- zero g_delta, then make it visible before any publish ---
    if (blk < BB && tid < TP1) g_delta[blk * TP1 + tid] = 0.0;
    grid_barrier(7);

    // ============ Phase A: precompute D + delta0 (strided tiles in batch) ===
    for (int ti = jj; ti < NTIL; ti += BPB) {
        const int p0 = ti * 64;

        if (tid < 64) {
            float xv = x[b * HW + p0 + tid];
            float bv = bg[p0 + tid];
            sm.pre.xs[tid] = xv;
            float e = xv - bv;
            sm.pre.eb[tid] = e * e;
            g_topcov[b * HW + p0 + tid] = 0;
        }
        __syncthreads();

        const int ts  = tid >> 4;        // 16 templates per iteration
        const int ps4 = tid & 15;        // float4 pixel group
        #pragma unroll
        for (int t16 = 0; t16 < TT; t16 += 16) {
            int t = t16 + ts;
            const size_t rb = (size_t)(b * TT + t) * HW + p0;
            float4 tv = __ldg((const float4*)(temps + rb) + ps4);
            float4 mv = __ldg((const float4*)(msks  + rb) + ps4);
            int p = 4 * ps4;
            float d0 = 0.f, d1 = 0.f, d2 = 0.f, d3 = 0.f;
            if (mv.x > MTHR) { float a = sm.pre.xs[p]     - tv.x * mv.x; d0 = a * a - sm.pre.eb[p];     }
            if (mv.y > MTHR) { float a = sm.pre.xs[p + 1] - tv.y * mv.y; d1 = a * a - sm.pre.eb[p + 1]; }
            if (mv.z > MTHR) { float a = sm.pre.xs[p + 2] - tv.z * mv.z; d2 = a * a - sm.pre.eb[p + 2]; }
            if (mv.w > MTHR) { float a = sm.pre.xs[p + 3] - tv.w * mv.w; d3 = a * a - sm.pre.eb[p + 3]; }
            sm.pre.dsm[p][t]     = d0;
            sm.pre.dsm[p + 1][t] = d1;
            sm.pre.dsm[p + 2][t] = d2;
            sm.pre.dsm[p + 3][t] = d3;
        }
        __syncthreads();

        const size_t obase = ((size_t)b * HW + p0) * TT;
        for (int i = tid; i < 64 * TT / 4; i += 256) {
            int r = i / 24, c = (i % 24) * 4;
            float4 v = make_float4(sm.pre.dsm[r][c], sm.pre.dsm[r][c + 1],
                                   sm.pre.dsm[r][c + 2], sm.pre.dsm[r][c + 3]);
            *(float4*)&g_D[obase + (size_t)i * 4] = v;
        }

        if (tid < TT) {
            float s = 0.f;
            #pragma unroll
            for (int p = 0; p < 64; p++) s += sm.pre.dsm[p][tid];
            accd[tid] += s;
        }
        __syncthreads();   // protect smem reuse next tile
    }
    if (tid < TT)
        atomicAdd(&g_delta[b * TP1 + 1 + tid], (double)accd[tid]);

    grid_barrier(0);

    // ============ Phase B: 6 greedy steps on own contiguous slice ==========
    const int pstart = (jj * HW) / BPB;
    const int pend   = ((jj + 1) * HW) / BPB;
    const int len    = pend - pstart;       // 455 or 456

    for (int s = 0; s < NSTEP; s++) {
        // --- argmin over 97 candidates (redundant per block, identical) ---
        if (tid < 32) {
            double bestv = 1e300;
            int    besti = TP1;
            for (int t = tid; t < TP1; t += 32) {
                double v = __ldcg(&g_delta[b * TP1 + t]);
                if (used[t]) v = 1e30;
                if (v < bestv) { bestv = v; besti = t; }   // earliest on tie
            }
            for (int off = 16; off; off >>= 1) {
                double ov = __shfl_down_sync(0xffffffffu, bestv, off);
                int    oi = __shfl_down_sync(0xffffffffu, besti, off);
                if (ov < bestv || (ov == bestv && oi < besti)) { bestv = ov; besti = oi; }
            }
            if (tid == 0) {
                sm.st.scid = besti;
                if (besti != 0) used[besti] = 1;
            }
        }
        __syncthreads();
        const int cid = sm.st.scid;

        // --- paint own pixels + deterministic compaction of new ones ---
        int base = 0;
        if (cid != 0) {
            const size_t mrow = (size_t)(b * TT + cid - 1) * HW;
            #pragma unroll
            for (int k = 0; k < 2; k++) {
                int lp = k * 256 + tid;
                int p  = pstart + lp;
                bool nw = false;
                if (lp < len) {
                    int q = b * HW + p;
                    float mv = msks[mrow + p];
                    if (mv > MTHR && !g_topcov[q]) {
                        g_topval[q] = temps[mrow + p] * mv;  // goes UNDER existing
                        g_topcov[q] = 1;
                        nw = true;
                    }
                }
                unsigned m = __ballot_sync(0xffffffffu, nw);
                if ((tid & 31) == 0) sm.st.wm[tid >> 5] = m;
                __syncthreads();
                int off = base, tot = 0;
                #pragma unroll
                for (int w = 0; w < 8; w++) {
                    int c = __popc(sm.st.wm[w]);
                    if (w < (tid >> 5)) off += c;
                    tot += c;
                }
                if (nw) sm.st.list[off + __popc(m & ((1u << (tid & 31)) - 1))] = lp;
                base += tot;
                __syncthreads();
            }
        }
        const int n = base;

        if (s == NSTEP - 1) {
            // --- final composition for own pixels ---
            #pragma unroll
            for (int k = 0; k < 2; k++) {
                int lp = k * 256 + tid;
                if (lp < len) {
                    int p = pstart + lp;
                    int q = b * HW + p;
                    out[q] = g_topcov[q] ? g_topval[q] : bg[p];
                }
            }
        } else {
            // --- gather-subtract D rows of own new pixels ---
            if (n > 0) {
                const int grp = tid >> 7;    // 0/1: even/odd list entries
                const int lt  = tid & 127;
                float a0 = 0.f, a1 = 0.f, a2 = 0.f, a3 = 0.f;
                if (lt < TT) {
                    const float* Db = g_D + ((size_t)b * HW + pstart) * TT + lt;
                    int j = grp;
                    for (; j + 6 < n; j += 8) {
                        a0 += Db[(size_t)sm.st.list[j    ] * TT];
                        a1 += Db[(size_t)sm.st.list[j + 2] * TT];
                        a2 += Db[(size_t)sm.st.list[j + 4] * TT];
                        a3 += Db[(size_t)sm.st.list[j + 6] * TT];
                    }
                    for (; j < n; j += 2) a0 += Db[(size_t)sm.st.list[j] * TT];
                    sm.st.partial[grp][lt] = (a0 + a1) + (a2 + a3);
                }
                __syncthreads();
                if (tid < TT) {
                    float tot2 = sm.st.partial[0][tid] + sm.st.partial[1][tid];
                    atomicAdd(&g_delta[b * TP1 + 1 + tid], -(double)tot2);
                }
            }
            grid_barrier(1 + s);
        }
    }
}

// ---------------------------------------------------------------------------
extern "C" void kernel_launch(void* const* d_in, const int* in_sizes, int n_in,
                              void* d_out, int out_size) {
    const float* x      = (const float*)d_in[0];   // (16,1,128,128)
    const float* temps  = (const float*)d_in[1];   // (16,96,1,128,128)
    const float* msks   = (const float*)d_in[2];   // (16,96,1,128,128)
    const float* bg     = (const float*)d_in[3];   // (1,128,128)
    float* out = (float*)d_out;                    // (16,1,128,128)

    k_all<<<NBLK, 256>>>(x, temps, msks, bg, out);
}

// round 12
// speedup vs baseline: 1.3931x; 1.1586x over previous
#include <cuda_runtime.h>
#include <cuda_fp16.h>

#define BB 16
#define TT 96
#define TP1 97
#define HW 16384
#define NSTEP 6
#define MTHR 0.9f
#define NBLK 512            // 4 blocks/SM * 148 SMs = 592 >= 512 (co-resident)
#define PXB 512             // pixels owned per block (both phases)
#define BPB 32              // blocks per batch (256 tiles / 8 per block: balanced)

// ---- scratch (device globals; no allocation APIs) ----
__device__ __half        g_D[(size_t)BB * HW * TT]; // d[b][p][t] fp16, t contiguous (~50MB)
__device__ double        g_delta[BB * TP1];         // idx0 = empty template, always 0
__device__ unsigned char g_topcov[BB * HW];
__device__ float         g_topval[BB * HW];
__device__ int           g_bcnt[8];                 // barrier arrival counters
__device__ int           g_bgen[8];                 // barrier generations (monotonic)

// ---------------------------------------------------------------------------
// Grid-wide sense-reversing barrier; gen is monotonic (graph-replay safe).
__device__ __forceinline__ void grid_barrier(int slot) {
    __syncthreads();
    __threadfence();
    if (threadIdx.x == 0) {
        int g   = atomicAdd(&g_bgen[slot], 0);
        int old = atomicAdd(&g_bcnt[slot], 1);
        if (old == NBLK - 1) {
            g_bcnt[slot] = 0;
            __threadfence();
            atomicExch(&g_bgen[slot], g + 1);
        } else {
            while (atomicAdd(&g_bgen[slot], 0) == g) __nanosleep(64);
        }
    }
    __syncthreads();
    __threadfence();
}

// ---------------------------------------------------------------------------
struct SmemPre { float xs[64]; float eb[64]; float dsm[64][TP1]; };
struct SmemStep { int list[PXB]; float partial[2][TT]; unsigned wm[8]; int scid; };
union SmemU { SmemPre pre; SmemStep st; };

__global__ void __launch_bounds__(256, 4)
k_all(const float* __restrict__ x,
      const float* __restrict__ temps,
      const float* __restrict__ msks,
      const float* __restrict__ bg,
      float* __restrict__ out) {
    __shared__ SmemU sm;
    __shared__ float accd[TT];           // phase-A delta0 accumulator (of rounded values)
    __shared__ unsigned char used[TP1];

    const int tid = threadIdx.x;
    const int blk = blockIdx.x;
    const int b   = blk >> 5;            // 32 blocks per batch
    const int jj  = blk & 31;
    const int p0g = jj * PXB;            // block's 512-pixel slice

    if (tid < TP1) used[tid] = 0;
    if (tid < TT)  accd[tid] = 0.f;

    // --- zero g_delta, visible before any publish ---
    if (blk < BB && tid < TP1) g_delta[blk * TP1 + tid] = 0.0;
    grid_barrier(7);

    // ============ Phase A: precompute D (fp16) + delta0 on own 8 tiles ======
    for (int ti = 0; ti < 8; ti++) {
        const int p0 = p0g + ti * 64;

        if (tid < 64) {
            float xv = x[b * HW + p0 + tid];
            float bv = bg[p0 + tid];
            sm.pre.xs[tid] = xv;
            float e = xv - bv;
            sm.pre.eb[tid] = e * e;
            g_topcov[b * HW + p0 + tid] = 0;
        }
        __syncthreads();

        const int ts  = tid >> 4;        // 16 templates per iteration
        const int ps4 = tid & 15;        // float4 pixel group
        #pragma unroll
        for (int t16 = 0; t16 < TT; t16 += 16) {
            int t = t16 + ts;
            const size_t rb = (size_t)(b * TT + t) * HW + p0;
            float4 tv = __ldcs((const float4*)(temps + rb) + ps4);  // stream, evict-first
            float4 mv = __ldcs((const float4*)(msks  + rb) + ps4);
            int p = 4 * ps4;
            float d0 = 0.f, d1 = 0.f, d2 = 0.f, d3 = 0.f;
            if (mv.x > MTHR) { float a = sm.pre.xs[p]     - tv.x * mv.x; d0 = a * a - sm.pre.eb[p];     }
            if (mv.y > MTHR) { float a = sm.pre.xs[p + 1] - tv.y * mv.y; d1 = a * a - sm.pre.eb[p + 1]; }
            if (mv.z > MTHR) { float a = sm.pre.xs[p + 2] - tv.z * mv.z; d2 = a * a - sm.pre.eb[p + 2]; }
            if (mv.w > MTHR) { float a = sm.pre.xs[p + 3] - tv.w * mv.w; d3 = a * a - sm.pre.eb[p + 3]; }
            sm.pre.dsm[p][t]     = d0;
            sm.pre.dsm[p + 1][t] = d1;
            sm.pre.dsm[p + 2][t] = d2;
            sm.pre.dsm[p + 3][t] = d3;
        }
        __syncthreads();

        // pack + store D as fp16, t-contiguous: 64*96 halves = 768 uint4
        {
            __half* dst = g_D + ((size_t)b * HW + p0) * TT;
            for (int i = tid; i < 768; i += 256) {
                int r = i / 12, c = (i % 12) * 8;
                __half2 h0 = __floats2half2_rn(sm.pre.dsm[r][c    ], sm.pre.dsm[r][c + 1]);
                __half2 h1 = __floats2half2_rn(sm.pre.dsm[r][c + 2], sm.pre.dsm[r][c + 3]);
                __half2 h2 = __floats2half2_rn(sm.pre.dsm[r][c + 4], sm.pre.dsm[r][c + 5]);
                __half2 h3 = __floats2half2_rn(sm.pre.dsm[r][c + 6], sm.pre.dsm[r][c + 7]);
                uint4 v = make_uint4(*(unsigned*)&h0, *(unsigned*)&h1,
                                     *(unsigned*)&h2, *(unsigned*)&h3);
                *(uint4*)(dst + (size_t)i * 8) = v;
            }
        }

        // delta0 from the SAME half-rounded values (exact incremental invariant)
        if (tid < TT) {
            float s = 0.f;
            #pragma unroll
            for (int p = 0; p < 64; p++)
                s += __half2float(__float2half_rn(sm.pre.dsm[p][tid]));
            accd[tid] += s;
        }
        __syncthreads();   // protect smem reuse next tile
    }
    if (tid < TT)
        atomicAdd(&g_delta[b * TP1 + 1 + tid], (double)accd[tid]);

    grid_barrier(0);

    // ============ Phase B: 6 greedy steps on own 512 pixels ================
    for (int s = 0; s < NSTEP; s++) {
        // --- argmin over 97 candidates (redundant per block, identical) ---
        if (tid < 32) {
            double bestv = 1e300;
            int    besti = TP1;
            for (int t = tid; t < TP1; t += 32) {
                double v = __ldcg(&g_delta[b * TP1 + t]);
                if (used[t]) v = 1e30;
                if (v < bestv) { bestv = v; besti = t; }   // earliest on tie
            }
            for (int off = 16; off; off >>= 1) {
                double ov = __shfl_down_sync(0xffffffffu, bestv, off);
                int    oi = __shfl_down_sync(0xffffffffu, besti, off);
                if (ov < bestv || (ov == bestv && oi < besti)) { bestv = ov; besti = oi; }
            }
            if (tid == 0) {
                sm.st.scid = besti;
                if (besti != 0) used[besti] = 1;
            }
        }
        __syncthreads();
        const int cid = sm.st.scid;

        // --- paint own pixels + deterministic compaction of new ones ---
        int base = 0;
        if (cid != 0) {
            const size_t mrow = (size_t)(b * TT + cid - 1) * HW;
            #pragma unroll
            for (int k = 0; k < PXB / 256; k++) {
                int lp = k * 256 + tid;
                int p  = p0g + lp;
                int q  = b * HW + p;
                bool nw = false;
                float mv = msks[mrow + p];
                if (mv > MTHR && !g_topcov[q]) {
                    g_topval[q] = temps[mrow + p] * mv;  // goes UNDER existing
                    g_topcov[q] = 1;
                    nw = true;
                }
                unsigned m = __ballot_sync(0xffffffffu, nw);
                if ((tid & 31) == 0) sm.st.wm[tid >> 5] = m;
                __syncthreads();
                int off = base, tot = 0;
                #pragma unroll
                for (int w = 0; w < 8; w++) {
                    int c = __popc(sm.st.wm[w]);
                    if (w < (tid >> 5)) off += c;
                    tot += c;
                }
                if (nw) sm.st.list[off + __popc(m & ((1u << (tid & 31)) - 1))] = lp;
                base += tot;
                __syncthreads();
            }
        }
        const int n = base;

        if (s == NSTEP - 1) {
            // --- final composition for own pixels ---
            #pragma unroll
            for (int k = 0; k < PXB / 256; k++) {
                int p = p0g + k * 256 + tid;
                int q = b * HW + p;
                out[q] = g_topcov[q] ? g_topval[q] : bg[p];
            }
        } else {
            // --- gather-subtract fp16 D rows of own new pixels ---
            if (n > 0) {
                const int grp = tid >> 7;    // 0/1: even/odd list entries
                const int lt  = tid & 127;
                float a0 = 0.f, a1 = 0.f, a2 = 0.f, a3 = 0.f;
                if (lt < TT) {
                    const __half* Db = g_D + ((size_t)b * HW + p0g) * TT + lt;
                    int j = grp;
                    for (; j + 6 < n; j += 8) {
                        a0 += __half2float(Db[(size_t)sm.st.list[j    ] * TT]);
                        a1 += __half2float(Db[(size_t)sm.st.list[j + 2] * TT]);
                        a2 += __half2float(Db[(size_t)sm.st.list[j + 4] * TT]);
                        a3 += __half2float(Db[(size_t)sm.st.list[j + 6] * TT]);
                    }
                    for (; j < n; j += 2) a0 += __half2float(Db[(size_t)sm.st.list[j] * TT]);
                    sm.st.partial[grp][lt] = (a0 + a1) + (a2 + a3);
                }
                __syncthreads();
                if (tid < TT) {
                    float tot2 = sm.st.partial[0][tid] + sm.st.partial[1][tid];
                    atomicAdd(&g_delta[b * TP1 + 1 + tid], -(double)tot2);
                }
            }
            grid_barrier(1 + s);
        }
    }
}

// ---------------------------------------------------------------------------
extern "C" void kernel_launch(void* const* d_in, const int* in_sizes, int n_in,
                              void* d_out, int out_size) {
    const float* x      = (const float*)d_in[0];   // (16,1,128,128)
    const float* temps  = (const float*)d_in[1];   // (16,96,1,128,128)
    const float* msks   = (const float*)d_in[2];   // (16,96,1,128,128)
    const float* bg     = (const float*)d_in[3];   // (1,128,128)
    float* out = (float*)d_out;                    // (16,1,128,128)

    k_all<<<NBLK, 256>>>(x, temps, msks, bg, out);
}